// round 13
// baseline (speedup 1.0000x reference)
#include <cuda_runtime.h>
#include <cuda_bf16.h>
#include <math.h>

#define Bsz 256
#define Ssz 50
#define Csz 40
#define Dsz 256
#define TDIFF 1000

#define LSTM_GX 16
#define LSTM_GY 8

// ---------------- scratch ----------------
__device__ float g_x[Bsz*Ssz*Dsz];
__device__ float g_Gih[Bsz*Ssz*4*Dsz];      // x@Wih^T + (bih+bhh)
__device__ float g_hbuf[2][Bsz*Dsz];
__device__ float g_w[Bsz*Ssz*Dsz];
__device__ float g_featE[Bsz*64];
__device__ float g_featW[Bsz*Ssz*64];
__device__ float g_aligned[Bsz*Ssz*Dsz];
__device__ float g_alpha[Bsz];
__device__ float g_WdiffT[Dsz*Dsz];
__device__ float g_bsum[4*Dsz];

// bf16 split copies (hi + lo)
__device__ __nv_bfloat16 g_xhi[Bsz*Ssz*Dsz],   g_xlo[Bsz*Ssz*Dsz];
__device__ __nv_bfloat16 g_rnnhi[Bsz*Ssz*Dsz], g_rnnlo[Bsz*Ssz*Dsz];
__device__ __nv_bfloat16 g_prehi[Bsz*Ssz*Dsz], g_prelo[Bsz*Ssz*Dsz];
__device__ __nv_bfloat16 g_Wihhi[4*Dsz*Dsz],   g_Wihlo[4*Dsz*Dsz];
__device__ __nv_bfloat16 g_Whkhi[Dsz*Dsz],     g_Whklo[Dsz*Dsz];
__device__ __nv_bfloat16 g_Wdhi[Dsz*Dsz],      g_Wdlo[Dsz*Dsz];

__device__ unsigned g_barCnt[LSTM_GY];
__device__ volatile unsigned g_barGen[LSTM_GY];

// ================= helpers =================
__device__ __forceinline__ unsigned smem_u32(const void* p)
{
    unsigned a;
    asm("{ .reg .u64 t; cvta.to.shared.u64 t, %1; cvt.u32.u64 %0, t; }"
        : "=r"(a) : "l"(p));
    return a;
}

__device__ __forceinline__ void cp_async16(unsigned dst, const void* src)
{
    asm volatile("cp.async.cg.shared.global [%0], [%1], 16;"
                 :: "r"(dst), "l"(src) : "memory");
}
#define CP_COMMIT() asm volatile("cp.async.commit_group;" ::: "memory")
#define CP_WAIT1()  asm volatile("cp.async.wait_group 1;" ::: "memory")
#define CP_WAIT0()  asm volatile("cp.async.wait_group 0;" ::: "memory")

__device__ __forceinline__ void mma16816(float* c, const unsigned* a, const unsigned* b)
{
    asm volatile(
        "mma.sync.aligned.m16n8k16.row.col.f32.bf16.bf16.f32 "
        "{%0,%1,%2,%3}, {%4,%5,%6,%7}, {%8,%9}, {%0,%1,%2,%3};"
        : "+f"(c[0]), "+f"(c[1]), "+f"(c[2]), "+f"(c[3])
        : "r"(a[0]), "r"(a[1]), "r"(a[2]), "r"(a[3]), "r"(b[0]), "r"(b[1]));
}

// ================= pipelined bf16 split-GEMM (HMMA + cp.async) =================
#define GPAD 72
#define GTILE (128*GPAD)                 // bf16 per tile
#define GSTAGE (4*GTILE)                 // 4 tiles (Ah,Al,Bh,Bl) per stage
#define GM_SMEM (2*GSTAGE*2)             // 2 stages, bytes = 147456

__device__ __forceinline__ void stage_load(
    __nv_bfloat16* base,
    const __nv_bfloat16* __restrict__ Ahi, const __nv_bfloat16* __restrict__ Alo,
    const __nv_bfloat16* __restrict__ Bhi, const __nv_bfloat16* __restrict__ Blo,
    int m0, int n0, int kc, int tid)
{
    const int srow = tid >> 1;
    const int scol = (tid & 1) * 32;
    size_t goffA = (size_t)(m0 + srow) * 256 + kc + scol;
    size_t goffB = (size_t)(n0 + srow) * 256 + kc + scol;
    unsigned sb = smem_u32(base) + (srow * GPAD + scol) * 2;
    #pragma unroll
    for (int v = 0; v < 4; v++) {
        cp_async16(sb + v*16,                 Ahi + goffA + v*8);
        cp_async16(sb + GTILE*2 + v*16,       Alo + goffA + v*8);
        cp_async16(sb + 2*GTILE*2 + v*16,     Bhi + goffB + v*8);
        cp_async16(sb + 3*GTILE*2 + v*16,     Blo + goffB + v*8);
    }
}

__device__ __forceinline__ void stage_compute(
    const __nv_bfloat16* base, float acc[2][8][4],
    int wm, int wn, int r, int q)
{
    const __nv_bfloat16* sAh = base;
    const __nv_bfloat16* sAl = sAh + GTILE;
    const __nv_bfloat16* sBh = sAl + GTILE;
    const __nv_bfloat16* sBl = sBh + GTILE;
    #pragma unroll
    for (int kk = 0; kk < 4; kk++) {
        const int kb = kk * 16 + 2 * q;
        unsigned ah[2][4], al[2][4], bh[8][2], bl[8][2];
        #pragma unroll
        for (int mi = 0; mi < 2; mi++) {
            int base2 = (wm + mi*16 + r) * GPAD + kb;
            ah[mi][0] = *(const unsigned*)(sAh + base2);
            ah[mi][1] = *(const unsigned*)(sAh + base2 + 8*GPAD);
            ah[mi][2] = *(const unsigned*)(sAh + base2 + 8);
            ah[mi][3] = *(const unsigned*)(sAh + base2 + 8*GPAD + 8);
            al[mi][0] = *(const unsigned*)(sAl + base2);
            al[mi][1] = *(const unsigned*)(sAl + base2 + 8*GPAD);
            al[mi][2] = *(const unsigned*)(sAl + base2 + 8);
            al[mi][3] = *(const unsigned*)(sAl + base2 + 8*GPAD + 8);
        }
        #pragma unroll
        for (int ni = 0; ni < 8; ni++) {
            int base2 = (wn + ni*8 + r) * GPAD + kb;
            bh[ni][0] = *(const unsigned*)(sBh + base2);
            bh[ni][1] = *(const unsigned*)(sBh + base2 + 8);
            bl[ni][0] = *(const unsigned*)(sBl + base2);
            bl[ni][1] = *(const unsigned*)(sBl + base2 + 8);
        }
        #pragma unroll
        for (int mi = 0; mi < 2; mi++)
            #pragma unroll
            for (int ni = 0; ni < 8; ni++) {
                mma16816(acc[mi][ni], ah[mi], bh[ni]);
                mma16816(acc[mi][ni], ah[mi], bl[ni]);
                mma16816(acc[mi][ni], al[mi], bh[ni]);
            }
    }
}

__global__ void __launch_bounds__(256, 1)
gemm_mma(const __nv_bfloat16* __restrict__ Ahi, const __nv_bfloat16* __restrict__ Alo,
         const __nv_bfloat16* __restrict__ Bhi, const __nv_bfloat16* __restrict__ Blo,
         const float* __restrict__ bias, float* __restrict__ C, int ldc)
{
    extern __shared__ __nv_bfloat16 sm[];
    const int tid = threadIdx.x;
    const int w   = tid >> 5;
    const int l   = tid & 31;
    const int wm  = (w >> 1) * 32;
    const int wn  = (w & 1) * 64;
    const int r   = l >> 2;
    const int q   = l & 3;
    const int m0  = blockIdx.y * 128;
    const int n0  = blockIdx.x * 128;

    float acc[2][8][4];
    #pragma unroll
    for (int mi = 0; mi < 2; mi++)
        #pragma unroll
        for (int ni = 0; ni < 8; ni++)
            #pragma unroll
            for (int e = 0; e < 4; e++) acc[mi][ni][e] = 0.f;

    // prologue: stage 0
    stage_load(sm, Ahi, Alo, Bhi, Blo, m0, n0, 0, tid);
    CP_COMMIT();

    for (int i = 0; i < 4; i++) {
        __nv_bfloat16* cur = sm + (i & 1) * GSTAGE;
        if (i < 3) {
            stage_load(sm + ((i + 1) & 1) * GSTAGE, Ahi, Alo, Bhi, Blo,
                       m0, n0, (i + 1) * 64, tid);
            CP_COMMIT();
            CP_WAIT1();
        } else {
            CP_WAIT0();
        }
        __syncthreads();
        stage_compute(cur, acc, wm, wn, r, q);
        __syncthreads();
    }

    #pragma unroll
    for (int mi = 0; mi < 2; mi++) {
        int row = m0 + wm + mi*16 + r;
        #pragma unroll
        for (int ni = 0; ni < 8; ni++) {
            int col = n0 + wn + ni*8 + 2*q;
            float b0 = bias[col], b1 = bias[col + 1];
            *(float2*)(C + (size_t)row * ldc + col) =
                make_float2(acc[mi][ni][0] + b0, acc[mi][ni][1] + b1);
            *(float2*)(C + (size_t)(row + 8) * ldc + col) =
                make_float2(acc[mi][ni][2] + b0, acc[mi][ni][3] + b1);
        }
    }
}

// ---------------- fused weight splits (Wih, Whk, WdiffT) ----------------
#define DD (Dsz*Dsz)
__global__ void wsplit_all(const float* __restrict__ Wih,
                           const float* __restrict__ Whk)
{
    int i = blockIdx.x * 256 + threadIdx.x;
    float x;
    __nv_bfloat16 *hi, *lo;
    int idx;
    if (i < 4*DD)       { x = Wih[i];            hi = g_Wihhi; lo = g_Wihlo; idx = i; }
    else if (i < 5*DD)  { idx = i - 4*DD; x = Whk[idx];      hi = g_Whkhi; lo = g_Whklo; }
    else                { idx = i - 5*DD; x = g_WdiffT[idx]; hi = g_Wdhi;  lo = g_Wdlo; }
    __nv_bfloat16 h = __float2bfloat16(x);
    hi[idx] = h;
    lo[idx] = __float2bfloat16(x - __bfloat162float(h));
}

// ================= 64x64 NT GEMM (N=64 feature GEMMs) =================
__global__ void gemm_nt(int M, int N, int K,
                        const float* __restrict__ A, int lda,
                        const float* __restrict__ B, int ldb,
                        const float* __restrict__ bias,
                        float* __restrict__ C, int ldc)
{
    __shared__ float As[16][68];
    __shared__ float Bsh[16][68];
    const int tid = threadIdx.x;
    const int m0 = blockIdx.y * 64;
    const int n0 = blockIdx.x * 64;
    const int tx = tid & 15;
    const int ty = tid >> 4;
    const int lr = tid >> 2;
    const int lc = (tid & 3) * 4;

    float acc[4][4] = {};
    for (int k0 = 0; k0 < K; k0 += 16) {
        float4 a4 = *(const float4*)(A + (size_t)(m0 + lr) * lda + k0 + lc);
        float4 b4 = *(const float4*)(B + (size_t)(n0 + lr) * ldb + k0 + lc);
        As[lc+0][lr] = a4.x; As[lc+1][lr] = a4.y; As[lc+2][lr] = a4.z; As[lc+3][lr] = a4.w;
        Bsh[lc+0][lr] = b4.x; Bsh[lc+1][lr] = b4.y; Bsh[lc+2][lr] = b4.z; Bsh[lc+3][lr] = b4.w;
        __syncthreads();
        #pragma unroll
        for (int k = 0; k < 16; k++) {
            float a[4], b[4];
            #pragma unroll
            for (int i = 0; i < 4; i++) a[i] = As[k][ty*4 + i];
            #pragma unroll
            for (int j = 0; j < 4; j++) b[j] = Bsh[k][tx*4 + j];
            #pragma unroll
            for (int i = 0; i < 4; i++)
                #pragma unroll
                for (int j = 0; j < 4; j++)
                    acc[i][j] = fmaf(a[i], b[j], acc[i][j]);
        }
        __syncthreads();
    }
    #pragma unroll
    for (int i = 0; i < 4; i++) {
        int row = m0 + ty*4 + i;
        #pragma unroll
        for (int j = 0; j < 4; j++) {
            int col = n0 + tx*4 + j;
            float v = acc[i][j];
            if (bias) v += bias[col];
            C[(size_t)row * ldc + col] = v;
        }
    }
}

// ---------------- embedding gather-sum (+ inline split) ----------------
__global__ void embed_kernel(const int* __restrict__ seqs,
                             const float* __restrict__ emb)
{
    int bs = blockIdx.x;
    int d  = threadIdx.x;
    __shared__ int idx[Csz];
    if (threadIdx.x < Csz) idx[threadIdx.x] = seqs[bs * Csz + threadIdx.x];
    __syncthreads();
    float acc = 0.f;
    #pragma unroll 8
    for (int c = 0; c < Csz; c++)
        acc += __ldg(emb + (size_t)idx[c] * Dsz + d);
    size_t o = (size_t)bs * Dsz + d;
    g_x[o] = acc;
    __nv_bfloat16 h = __float2bfloat16(acc);
    g_xhi[o] = h;
    g_xlo[o] = __float2bfloat16(acc - __bfloat162float(h));
}

// ---------------- alpha lookup ----------------
__global__ void alpha_kernel(const int* __restrict__ t)
{
    __shared__ float tab[TDIFF];
    if (threadIdx.x == 0) {
        float a = 1.f;
        for (int i = 0; i < TDIFF; i++) {
            float beta = 1e-4f + (0.02f - 1e-4f) * (float)i / (float)(TDIFF - 1);
            a *= (1.f - beta);
            tab[i] = a;
        }
    }
    __syncthreads();
    if (threadIdx.x < Bsz) g_alpha[threadIdx.x] = tab[t[threadIdx.x]];
}

// ---------------- bias sum ----------------
__global__ void bsum_kernel(const float* __restrict__ bih,
                            const float* __restrict__ bhh)
{
    int i = blockIdx.x * 256 + threadIdx.x;
    g_bsum[i] = bih[i] + bhh[i];
}

__global__ void transpose_wdiff(const float* __restrict__ Wdiff)
{
    int n = blockIdx.x, k = threadIdx.x;
    g_WdiffT[n * Dsz + k] = __ldg(Wdiff + k * Dsz + n);
}

// ---------------- fused persistent LSTM (256 thr, hbuf, group barrier) ----------------
__device__ __forceinline__ float sigf(float x) { return 1.f / (1.f + expf(-x)); }

__device__ __forceinline__ void groupBarrier(int grp)
{
    __syncthreads();
    if (threadIdx.x == 0) {
        __threadfence();
        unsigned gen = g_barGen[grp];
        __threadfence();
        if (atomicAdd(&g_barCnt[grp], 1u) == LSTM_GX - 1) {
            g_barCnt[grp] = 0;
            __threadfence();
            g_barGen[grp] = gen + 1;
        } else {
            while (g_barGen[grp] == gen) __nanosleep(32);
        }
        __threadfence();
    }
    __syncthreads();
}

#define LSTM_SMEM ((256*68 + 256*36) * (int)sizeof(float))

__global__ void __launch_bounds__(256, 1)
lstm_fused(const float* __restrict__ Whh)
{
    extern __shared__ float sh[];
    float* Bsf = sh;               // [k][j*4+g], stride 68
    float* As  = sh + 256*68;      // [k][m],     stride 36

    const int tid = threadIdx.x;
    const int nb  = blockIdx.x;
    const int mb  = blockIdx.y;
    const int m0  = mb * 32;
    const int tx  = tid & 15;      // h-dim
    const int ty  = tid >> 4;      // 0..15: rows m0+ty*2+{0,1}
    const int d   = nb * 16 + tx;

    // one-time Whh slice, gate-interleaved: Bsf[k][j*4+g] = Whh[g*256+nb*16+j][k]
    {
        int r = tid >> 2;          // 0..63
        int g = r & 3, j = r >> 2;
        const float* src = Whh + (size_t)(g * 256 + nb * 16 + j) * 256;
        for (int q = (tid & 3); q < 64; q += 4) {
            float4 v = *(const float4*)(src + q * 4);
            Bsf[(q*4+0)*68 + r] = v.x;
            Bsf[(q*4+1)*68 + r] = v.y;
            Bsf[(q*4+2)*68 + r] = v.z;
            Bsf[(q*4+3)*68 + r] = v.w;
        }
    }
    float cst[2] = {0.f, 0.f};
    __syncthreads();

    for (int t = 0; t < Ssz; t++) {
        // prefetch Gih epilogue operands
        float pg[2][4];
        #pragma unroll
        for (int i = 0; i < 2; i++) {
            size_t gb = ((size_t)(m0 + ty*2 + i) * Ssz + t) * 1024 + d;
            pg[i][0] = __ldg(g_Gih + gb);
            pg[i][1] = __ldg(g_Gih + gb + 256);
            pg[i][2] = __ldg(g_Gih + gb + 512);
            pg[i][3] = __ldg(g_Gih + gb + 768);
        }

        float acc[2][4] = {};
        if (t > 0) {
            // stage h(t-1) tile 32x256 from contiguous hbuf, transposed
            const float* hsrc = g_hbuf[(t + 1) & 1] + (size_t)m0 * Dsz;
            int rr = tid >> 3;     // 0..31
            const float* arow = hsrc + (size_t)rr * Dsz;
            for (int q = (tid & 7); q < 64; q += 8) {
                float4 v = *(const float4*)(arow + q * 4);
                As[(q*4+0)*36 + rr] = v.x;
                As[(q*4+1)*36 + rr] = v.y;
                As[(q*4+2)*36 + rr] = v.z;
                As[(q*4+3)*36 + rr] = v.w;
            }
            __syncthreads();
            #pragma unroll 8
            for (int k = 0; k < 256; k++) {
                float2 a = *(const float2*)(As + k * 36 + ty * 2);
                float4 b = *(const float4*)(Bsf + k * 68 + tx * 4);
                acc[0][0] = fmaf(a.x, b.x, acc[0][0]);
                acc[0][1] = fmaf(a.x, b.y, acc[0][1]);
                acc[0][2] = fmaf(a.x, b.z, acc[0][2]);
                acc[0][3] = fmaf(a.x, b.w, acc[0][3]);
                acc[1][0] = fmaf(a.y, b.x, acc[1][0]);
                acc[1][1] = fmaf(a.y, b.y, acc[1][1]);
                acc[1][2] = fmaf(a.y, b.z, acc[1][2]);
                acc[1][3] = fmaf(a.y, b.w, acc[1][3]);
            }
        }
        float* hdst = g_hbuf[t & 1];
        #pragma unroll
        for (int i = 0; i < 2; i++) {
            int b = m0 + ty * 2 + i;
            float gi = acc[i][0] + pg[i][0];
            float gf = acc[i][1] + pg[i][1];
            float gg = acc[i][2] + pg[i][2];
            float go = acc[i][3] + pg[i][3];
            float iv = sigf(gi), fv = sigf(gf);
            float gv = tanhf(gg), ov = sigf(go);
            cst[i] = fv * cst[i] + iv * gv;
            float h = ov * tanhf(cst[i]);
            hdst[(size_t)b * Dsz + d] = h;
            // inline bf16 hi/lo split of h (consumed by w-GEMM)
            size_t o = ((size_t)b * Ssz + t) * Dsz + d;
            __nv_bfloat16 hh = __float2bfloat16(h);
            g_rnnhi[o] = hh;
            g_rnnlo[o] = __float2bfloat16(h - __bfloat162float(hh));
        }
        groupBarrier(mb);
    }
}

// ---------------- attention + aligned + diffusion prep (+ inline split) ----------------
__global__ void attn_diff(const float* __restrict__ W2,
                          const float* __restrict__ b2,
                          const float* __restrict__ noise,
                          const float* __restrict__ temb,
                          const int* __restrict__ tdi)
{
    int s = blockIdx.x;
    int b = blockIdx.y;
    int tid = threadIdx.x;
    const float* ek = g_x + (size_t)b * Ssz * Dsz;
    size_t orow = ((size_t)b * Ssz + s) * Dsz;

    float av;
    if (s == 0) {
        av = ek[tid];
    } else {
        __shared__ float s0[64], s1[64];
        __shared__ float a0s, a1s;
        int sm1 = s - 1;
        if (tid < 64) {
            float f = tanhf(g_featE[b*64 + tid] + g_featW[((size_t)b*Ssz + sm1)*64 + tid]);
            s0[tid] = f * W2[tid];
            s1[tid] = f * W2[64 + tid];
        }
        __syncthreads();
        if (tid == 0) {
            float l0 = b2[0], l1 = b2[1];
            for (int j = 0; j < 64; j++) { l0 += s0[j]; l1 += s1[j]; }
            float m = fmaxf(l0, l1);
            float e0 = expf(l0 - m), e1 = expf(l1 - m);
            float inv = 1.f / (e0 + e1);
            a0s = e0 * inv; a1s = e1 * inv;
        }
        __syncthreads();
        float wv = g_w[((size_t)b * Ssz + sm1) * Dsz + tid];
        av = a0s * ek[tid] + a1s * wv;
    }
    g_aligned[orow + tid] = av;
    float al = g_alpha[b];
    float sa = sqrtf(al), sn = sqrtf(1.f - al);
    float pre = av * sa + noise[orow + tid] * sn
              + temb[(size_t)tdi[b] * Dsz + tid];
    __nv_bfloat16 h = __float2bfloat16(pre);
    g_prehi[orow + tid] = h;
    g_prelo[orow + tid] = __float2bfloat16(pre - __bfloat162float(h));
}

// ---------------- fused max-pool + final projections ----------------
__global__ void poolfinal(const float* __restrict__ noise,
                          const float* __restrict__ pn,
                          const float* __restrict__ Wout,
                          const float* __restrict__ bout,
                          float* __restrict__ out)
{
    int b = blockIdx.x, d = threadIdx.x;
    float xm = -INFINITY, gm = -INFINITY;
    for (int s = 0; s < Ssz; s++) {
        size_t i = ((size_t)b * Ssz + s) * Dsz + d;
        xm = fmaxf(xm, g_x[i]);
        float gv = g_aligned[i] + noise[i] - pn[i];
        gm = fmaxf(gm, gv);
    }
    __shared__ float4 red[256];
    red[d] = make_float4(xm * Wout[d], xm * Wout[Dsz + d],
                         gm * Wout[d], gm * Wout[Dsz + d]);
    __syncthreads();
    for (int off = 128; off > 0; off >>= 1) {
        if (d < off) {
            float4 a = red[d], c = red[d + off];
            red[d] = make_float4(a.x + c.x, a.y + c.y, a.z + c.z, a.w + c.w);
        }
        __syncthreads();
    }
    if (d == 0) {
        float4 r = red[0];
        out[b*2 + 0]         = r.x + bout[0];
        out[b*2 + 1]         = r.y + bout[1];
        out[2*Bsz + b*2 + 0] = r.z + bout[0];
        out[2*Bsz + b*2 + 1] = r.w + bout[1];
    }
}

// ---------------- host ----------------
static float* symf(const void* s)
{
    void* p = nullptr;
    cudaGetSymbolAddress(&p, s);
    return (float*)p;
}
static __nv_bfloat16* symb(const void* s)
{
    void* p = nullptr;
    cudaGetSymbolAddress(&p, s);
    return (__nv_bfloat16*)p;
}

extern "C" void kernel_launch(void* const* d_in, const int* in_sizes, int n_in,
                              void* d_out, int out_size)
{
    const int*   seqs   = (const int*)  d_in[0];
    const int*   tdiff  = (const int*)  d_in[5];
    const float* noise  = (const float*)d_in[6];
    const float* emb    = (const float*)d_in[7];
    const float* Wih    = (const float*)d_in[8];
    const float* Whh    = (const float*)d_in[9];
    const float* bih    = (const float*)d_in[10];
    const float* bhh    = (const float*)d_in[11];
    const float* Whk    = (const float*)d_in[12];
    const float* bhk    = (const float*)d_in[13];
    const float* W1     = (const float*)d_in[14];
    const float* b1     = (const float*)d_in[15];
    const float* W2     = (const float*)d_in[16];
    const float* b2     = (const float*)d_in[17];
    const float* Wdiff  = (const float*)d_in[18];
    const float* bdiff  = (const float*)d_in[19];
    const float* temb   = (const float*)d_in[20];
    const float* Wout   = (const float*)d_in[21];
    const float* bout   = (const float*)d_in[22];
    float* out = (float*)d_out;

    float* p_x    = symf(g_x);
    float* p_Gih  = symf(g_Gih);
    float* p_w    = symf(g_w);
    float* p_fE   = symf(g_featE);
    float* p_fW   = symf(g_featW);
    float* p_bsum = symf(g_bsum);

    __nv_bfloat16* p_xhi   = symb(g_xhi);
    __nv_bfloat16* p_xlo   = symb(g_xlo);
    __nv_bfloat16* p_rhi   = symb(g_rnnhi);
    __nv_bfloat16* p_rlo   = symb(g_rnnlo);
    __nv_bfloat16* p_phi   = symb(g_prehi);
    __nv_bfloat16* p_plo   = symb(g_prelo);
    __nv_bfloat16* p_Wihhi = symb(g_Wihhi);
    __nv_bfloat16* p_Wihlo = symb(g_Wihlo);
    __nv_bfloat16* p_Whkhi = symb(g_Whkhi);
    __nv_bfloat16* p_Whklo = symb(g_Whklo);
    __nv_bfloat16* p_Wdhi  = symb(g_Wdhi);
    __nv_bfloat16* p_Wdlo  = symb(g_Wdlo);

    static bool attr_done = false;
    if (!attr_done) {
        cudaFuncSetAttribute(lstm_fused,
                             cudaFuncAttributeMaxDynamicSharedMemorySize, LSTM_SMEM);
        cudaFuncSetAttribute(gemm_mma,
                             cudaFuncAttributeMaxDynamicSharedMemorySize, GM_SMEM);
        attr_done = true;
    }

    const int BSD = Bsz * Ssz * Dsz;
    float* pn_out = out + 4 * Bsz;
    float* nn_out = out + 4 * Bsz + (size_t)BSD;

    // launches 1-4: prep (ordering puts gemm_mma(Gih) at launch #6 for ncu -s 5)
    alpha_kernel<<<1, 256>>>(tdiff);
    bsum_kernel<<<4, 256>>>(bih, bhh);
    transpose_wdiff<<<Dsz, Dsz>>>(Wdiff);
    wsplit_all<<<(6*DD)/256, 256>>>(Wih, Whk);

    // 5: embedding (+ inline split)
    embed_kernel<<<Bsz * Ssz, Dsz>>>(seqs, emb);

    // 6: Gih = x @ Wih^T + (bih+bhh)   (12800 x 1024, HMMA + cp.async pipeline)
    gemm_mma<<<dim3(8, 100), 256, GM_SMEM>>>(p_xhi, p_xlo, p_Wihhi, p_Wihlo,
                                             p_bsum, p_Gih, 4*Dsz);

    // 7: fused persistent LSTM (256 thr, writes split h inline)
    lstm_fused<<<dim3(LSTM_GX, LSTM_GY), 256, LSTM_SMEM>>>(Whh);

    // 8: w = rnn @ Whk^T + bhk
    gemm_mma<<<dim3(2, 100), 256, GM_SMEM>>>(p_rhi, p_rlo, p_Whkhi, p_Whklo,
                                             bhk, p_w, Dsz);

    // 9-10: attention features
    gemm_nt<<<dim3(1, Bsz/64), 256>>>(Bsz, 64, Dsz,
        p_x, Ssz * Dsz, W1, 2 * Dsz, b1, p_fE, 64);
    gemm_nt<<<dim3(1, (Bsz*Ssz)/64), 256>>>(Bsz*Ssz, 64, Dsz,
        p_w, Dsz, W1 + Dsz, 2 * Dsz, nullptr, p_fW, 64);

    // 11: attention softmax + aligned + diffusion prep
    attn_diff<<<dim3(Ssz, Bsz), Dsz>>>(W2, b2, noise, temb, tdiff);

    // 12: predicted_noise = pre @ Wdiff + bdiff
    gemm_mma<<<dim3(2, 100), 256, GM_SMEM>>>(p_phi, p_plo, p_Wdhi, p_Wdlo,
                                             bdiff, pn_out, Dsz);

    // 13: fused pool + final
    poolfinal<<<Bsz, Dsz>>>(noise, pn_out, Wout, bout, out);

    // 14: normal_noise passthrough
    cudaMemcpyAsync(nn_out, noise, (size_t)BSD * sizeof(float),
                    cudaMemcpyDeviceToDevice);
}

// round 14
// speedup vs baseline: 1.0600x; 1.0600x over previous
#include <cuda_runtime.h>
#include <cuda_bf16.h>
#include <math.h>

#define Bsz 256
#define Ssz 50
#define Csz 40
#define Dsz 256
#define TDIFF 1000

#define LSTM_GX 16
#define LSTM_GY 8

// ---------------- scratch ----------------
__device__ float g_x[Bsz*Ssz*Dsz];
__device__ float g_Gih[Bsz*Ssz*4*Dsz];      // x@Wih^T + (bih+bhh)
__device__ float g_hbuf[2][Bsz*Dsz];
__device__ float g_w[Bsz*Ssz*Dsz];
__device__ float g_featE[Bsz*64];
__device__ float g_featW[Bsz*Ssz*64];
__device__ float g_aligned[Bsz*Ssz*Dsz];
__device__ float g_alpha[Bsz];
__device__ float g_WdiffT[Dsz*Dsz];
__device__ float g_bsum[4*Dsz];

// bf16 split copies (hi + lo)
__device__ __nv_bfloat16 g_xhi[Bsz*Ssz*Dsz],   g_xlo[Bsz*Ssz*Dsz];
__device__ __nv_bfloat16 g_rnnhi[Bsz*Ssz*Dsz], g_rnnlo[Bsz*Ssz*Dsz];
__device__ __nv_bfloat16 g_prehi[Bsz*Ssz*Dsz], g_prelo[Bsz*Ssz*Dsz];
__device__ __nv_bfloat16 g_Wihhi[4*Dsz*Dsz],   g_Wihlo[4*Dsz*Dsz];
__device__ __nv_bfloat16 g_Whkhi[Dsz*Dsz],     g_Whklo[Dsz*Dsz];
__device__ __nv_bfloat16 g_Wdhi[Dsz*Dsz],      g_Wdlo[Dsz*Dsz];

__device__ unsigned g_barCnt[LSTM_GY];
__device__ volatile unsigned g_barGen[LSTM_GY];

// ================= mma.sync bf16 split-GEMM (HMMA; round-12 proven) =================
#define GPAD 72
#define GTILE (128*GPAD)
#define GM_SMEM (4*GTILE*2)

__device__ __forceinline__ void mma16816(float* c, const unsigned* a, const unsigned* b)
{
    asm volatile(
        "mma.sync.aligned.m16n8k16.row.col.f32.bf16.bf16.f32 "
        "{%0,%1,%2,%3}, {%4,%5,%6,%7}, {%8,%9}, {%0,%1,%2,%3};"
        : "+f"(c[0]), "+f"(c[1]), "+f"(c[2]), "+f"(c[3])
        : "r"(a[0]), "r"(a[1]), "r"(a[2]), "r"(a[3]), "r"(b[0]), "r"(b[1]));
}

__global__ void __launch_bounds__(256, 1)
gemm_mma(const __nv_bfloat16* __restrict__ Ahi, const __nv_bfloat16* __restrict__ Alo,
         const __nv_bfloat16* __restrict__ Bhi, const __nv_bfloat16* __restrict__ Blo,
         const float* __restrict__ bias, float* __restrict__ C, int ldc)
{
    extern __shared__ __nv_bfloat16 sm[];
    __nv_bfloat16* sAh = sm;
    __nv_bfloat16* sAl = sAh + GTILE;
    __nv_bfloat16* sBh = sAl + GTILE;
    __nv_bfloat16* sBl = sBh + GTILE;

    const int tid = threadIdx.x;
    const int w   = tid >> 5;
    const int l   = tid & 31;
    const int wm  = (w >> 1) * 32;
    const int wn  = (w & 1) * 64;
    const int r   = l >> 2;
    const int q   = l & 3;
    const int m0  = blockIdx.y * 128;
    const int n0  = blockIdx.x * 128;

    float acc[2][8][4];
    #pragma unroll
    for (int mi = 0; mi < 2; mi++)
        #pragma unroll
        for (int ni = 0; ni < 8; ni++)
            #pragma unroll
            for (int e = 0; e < 4; e++) acc[mi][ni][e] = 0.f;

    const int srow = tid >> 1;
    const int scol = (tid & 1) * 32;

    for (int kc = 0; kc < 256; kc += 64) {
        {
            size_t goffA = (size_t)(m0 + srow) * 256 + kc + scol;
            size_t goffB = (size_t)(n0 + srow) * 256 + kc + scol;
            int soff = srow * GPAD + scol;
            #pragma unroll
            for (int v = 0; v < 4; v++) {
                *(uint4*)(sAh + soff + v*8) = *(const uint4*)(Ahi + goffA + v*8);
                *(uint4*)(sAl + soff + v*8) = *(const uint4*)(Alo + goffA + v*8);
                *(uint4*)(sBh + soff + v*8) = *(const uint4*)(Bhi + goffB + v*8);
                *(uint4*)(sBl + soff + v*8) = *(const uint4*)(Blo + goffB + v*8);
            }
        }
        __syncthreads();

        #pragma unroll
        for (int kk = 0; kk < 4; kk++) {
            const int kb = kk * 16 + 2 * q;
            unsigned ah[2][4], al[2][4], bh[8][2], bl[8][2];
            #pragma unroll
            for (int mi = 0; mi < 2; mi++) {
                int base = (wm + mi*16 + r) * GPAD + kb;
                ah[mi][0] = *(const unsigned*)(sAh + base);
                ah[mi][1] = *(const unsigned*)(sAh + base + 8*GPAD);
                ah[mi][2] = *(const unsigned*)(sAh + base + 8);
                ah[mi][3] = *(const unsigned*)(sAh + base + 8*GPAD + 8);
                al[mi][0] = *(const unsigned*)(sAl + base);
                al[mi][1] = *(const unsigned*)(sAl + base + 8*GPAD);
                al[mi][2] = *(const unsigned*)(sAl + base + 8);
                al[mi][3] = *(const unsigned*)(sAl + base + 8*GPAD + 8);
            }
            #pragma unroll
            for (int ni = 0; ni < 8; ni++) {
                int base = (wn + ni*8 + r) * GPAD + kb;
                bh[ni][0] = *(const unsigned*)(sBh + base);
                bh[ni][1] = *(const unsigned*)(sBh + base + 8);
                bl[ni][0] = *(const unsigned*)(sBl + base);
                bl[ni][1] = *(const unsigned*)(sBl + base + 8);
            }
            #pragma unroll
            for (int mi = 0; mi < 2; mi++)
                #pragma unroll
                for (int ni = 0; ni < 8; ni++) {
                    mma16816(acc[mi][ni], ah[mi], bh[ni]);
                    mma16816(acc[mi][ni], ah[mi], bl[ni]);
                    mma16816(acc[mi][ni], al[mi], bh[ni]);
                }
        }
        __syncthreads();
    }

    #pragma unroll
    for (int mi = 0; mi < 2; mi++) {
        int row = m0 + wm + mi*16 + r;
        #pragma unroll
        for (int ni = 0; ni < 8; ni++) {
            int col = n0 + wn + ni*8 + 2*q;
            float b0 = bias[col], b1 = bias[col + 1];
            *(float2*)(C + (size_t)row * ldc + col) =
                make_float2(acc[mi][ni][0] + b0, acc[mi][ni][1] + b1);
            *(float2*)(C + (size_t)(row + 8) * ldc + col) =
                make_float2(acc[mi][ni][2] + b0, acc[mi][ni][3] + b1);
        }
    }
}

// ---------------- fused weight splits (Wih, Whk, WdiffT) ----------------
#define DD (Dsz*Dsz)
__global__ void wsplit_all(const float* __restrict__ Wih,
                           const float* __restrict__ Whk)
{
    int i = blockIdx.x * 256 + threadIdx.x;
    float x;
    __nv_bfloat16 *hi, *lo;
    int idx;
    if (i < 4*DD)       { x = Wih[i];            hi = g_Wihhi; lo = g_Wihlo; idx = i; }
    else if (i < 5*DD)  { idx = i - 4*DD; x = Whk[idx];      hi = g_Whkhi; lo = g_Whklo; }
    else                { idx = i - 5*DD; x = g_WdiffT[idx]; hi = g_Wdhi;  lo = g_Wdlo; }
    __nv_bfloat16 h = __float2bfloat16(x);
    hi[idx] = h;
    lo[idx] = __float2bfloat16(x - __bfloat162float(h));
}

// ================= 64x64 NT GEMM (N=64 feature GEMMs) =================
__global__ void gemm_nt(int M, int N, int K,
                        const float* __restrict__ A, int lda,
                        const float* __restrict__ B, int ldb,
                        const float* __restrict__ bias,
                        float* __restrict__ C, int ldc)
{
    __shared__ float As[16][68];
    __shared__ float Bsh[16][68];
    const int tid = threadIdx.x;
    const int m0 = blockIdx.y * 64;
    const int n0 = blockIdx.x * 64;
    const int tx = tid & 15;
    const int ty = tid >> 4;
    const int lr = tid >> 2;
    const int lc = (tid & 3) * 4;

    float acc[4][4] = {};
    for (int k0 = 0; k0 < K; k0 += 16) {
        float4 a4 = *(const float4*)(A + (size_t)(m0 + lr) * lda + k0 + lc);
        float4 b4 = *(const float4*)(B + (size_t)(n0 + lr) * ldb + k0 + lc);
        As[lc+0][lr] = a4.x; As[lc+1][lr] = a4.y; As[lc+2][lr] = a4.z; As[lc+3][lr] = a4.w;
        Bsh[lc+0][lr] = b4.x; Bsh[lc+1][lr] = b4.y; Bsh[lc+2][lr] = b4.z; Bsh[lc+3][lr] = b4.w;
        __syncthreads();
        #pragma unroll
        for (int k = 0; k < 16; k++) {
            float a[4], b[4];
            #pragma unroll
            for (int i = 0; i < 4; i++) a[i] = As[k][ty*4 + i];
            #pragma unroll
            for (int j = 0; j < 4; j++) b[j] = Bsh[k][tx*4 + j];
            #pragma unroll
            for (int i = 0; i < 4; i++)
                #pragma unroll
                for (int j = 0; j < 4; j++)
                    acc[i][j] = fmaf(a[i], b[j], acc[i][j]);
        }
        __syncthreads();
    }
    #pragma unroll
    for (int i = 0; i < 4; i++) {
        int row = m0 + ty*4 + i;
        #pragma unroll
        for (int j = 0; j < 4; j++) {
            int col = n0 + tx*4 + j;
            float v = acc[i][j];
            if (bias) v += bias[col];
            C[(size_t)row * ldc + col] = v;
        }
    }
}

// ---------------- embedding gather-sum (+ inline split) ----------------
__global__ void embed_kernel(const int* __restrict__ seqs,
                             const float* __restrict__ emb)
{
    int bs = blockIdx.x;
    int d  = threadIdx.x;
    __shared__ int idx[Csz];
    if (threadIdx.x < Csz) idx[threadIdx.x] = seqs[bs * Csz + threadIdx.x];
    __syncthreads();
    float acc = 0.f;
    #pragma unroll 8
    for (int c = 0; c < Csz; c++)
        acc += __ldg(emb + (size_t)idx[c] * Dsz + d);
    size_t o = (size_t)bs * Dsz + d;
    g_x[o] = acc;
    __nv_bfloat16 h = __float2bfloat16(acc);
    g_xhi[o] = h;
    g_xlo[o] = __float2bfloat16(acc - __bfloat162float(h));
}

// ---------------- alpha lookup ----------------
__global__ void alpha_kernel(const int* __restrict__ t)
{
    __shared__ float tab[TDIFF];
    if (threadIdx.x == 0) {
        float a = 1.f;
        for (int i = 0; i < TDIFF; i++) {
            float beta = 1e-4f + (0.02f - 1e-4f) * (float)i / (float)(TDIFF - 1);
            a *= (1.f - beta);
            tab[i] = a;
        }
    }
    __syncthreads();
    if (threadIdx.x < Bsz) g_alpha[threadIdx.x] = tab[t[threadIdx.x]];
}

// ---------------- bias sum ----------------
__global__ void bsum_kernel(const float* __restrict__ bih,
                            const float* __restrict__ bhh)
{
    int i = blockIdx.x * 256 + threadIdx.x;
    g_bsum[i] = bih[i] + bhh[i];
}

__global__ void transpose_wdiff(const float* __restrict__ Wdiff)
{
    int n = blockIdx.x, k = threadIdx.x;
    g_WdiffT[n * Dsz + k] = __ldg(Wdiff + k * Dsz + n);
}

// ---------------- fused persistent LSTM (round-12 proven 128-thr config
//                  + inline bf16 split of h in epilogue) ----------------
__device__ __forceinline__ float sigf(float x) { return 1.f / (1.f + expf(-x)); }

__device__ __forceinline__ void groupBarrier(int grp)
{
    __syncthreads();
    if (threadIdx.x == 0) {
        __threadfence();
        unsigned gen = g_barGen[grp];
        __threadfence();
        if (atomicAdd(&g_barCnt[grp], 1u) == LSTM_GX - 1) {
            g_barCnt[grp] = 0;
            __threadfence();
            g_barGen[grp] = gen + 1;
        } else {
            while (g_barGen[grp] == gen) __nanosleep(32);
        }
        __threadfence();
    }
    __syncthreads();
}

#define LSTM_SMEM ((256*68 + 256*36) * (int)sizeof(float))

__global__ void __launch_bounds__(128, 1)
lstm_fused(const float* __restrict__ Whh)
{
    extern __shared__ float sh[];
    float* Bsf = sh;               // [k][j*4+g], stride 68
    float* As  = sh + 256*68;      // [k][m],     stride 36

    const int tid = threadIdx.x;
    const int nb  = blockIdx.x;
    const int mb  = blockIdx.y;
    const int m0  = mb * 32;
    const int tx  = tid & 15;
    const int ty  = tid >> 4;
    const int d   = nb * 16 + tx;

    {
        int r = tid >> 1;
        int g = r & 3, j = r >> 2;
        const float* src = Whh + (size_t)(g * 256 + nb * 16 + j) * 256;
        for (int q = (tid & 1); q < 64; q += 2) {
            float4 v = *(const float4*)(src + q * 4);
            Bsf[(q*4+0)*68 + r] = v.x;
            Bsf[(q*4+1)*68 + r] = v.y;
            Bsf[(q*4+2)*68 + r] = v.z;
            Bsf[(q*4+3)*68 + r] = v.w;
        }
    }
    float cst[4] = {0.f, 0.f, 0.f, 0.f};
    __syncthreads();

    for (int t = 0; t < Ssz; t++) {
        // prefetch Gih epilogue operands (in flight during staging + compute)
        float pg[4][4];
        #pragma unroll
        for (int i = 0; i < 4; i++) {
            size_t gb = ((size_t)(m0 + ty*4 + i) * Ssz + t) * 1024 + d;
            pg[i][0] = __ldg(g_Gih + gb);
            pg[i][1] = __ldg(g_Gih + gb + 256);
            pg[i][2] = __ldg(g_Gih + gb + 512);
            pg[i][3] = __ldg(g_Gih + gb + 768);
        }

        float acc[4][4] = {};
        if (t > 0) {
            const float* hsrc = g_hbuf[(t + 1) & 1] + (size_t)m0 * Dsz;
            int rr = tid >> 2;
            const float* arow = hsrc + (size_t)rr * Dsz;
            for (int q = (tid & 3); q < 64; q += 4) {
                float4 v = *(const float4*)(arow + q * 4);
                As[(q*4+0)*36 + rr] = v.x;
                As[(q*4+1)*36 + rr] = v.y;
                As[(q*4+2)*36 + rr] = v.z;
                As[(q*4+3)*36 + rr] = v.w;
            }
            __syncthreads();
            #pragma unroll 8
            for (int k = 0; k < 256; k++) {
                float4 a = *(const float4*)(As + k * 36 + ty * 4);
                float4 b = *(const float4*)(Bsf + k * 68 + tx * 4);
                float av[4] = {a.x, a.y, a.z, a.w};
                float bv[4] = {b.x, b.y, b.z, b.w};
                #pragma unroll
                for (int i = 0; i < 4; i++)
                    #pragma unroll
                    for (int j = 0; j < 4; j++)
                        acc[i][j] = fmaf(av[i], bv[j], acc[i][j]);
            }
        }
        float* hdst = g_hbuf[t & 1];
        #pragma unroll
        for (int i = 0; i < 4; i++) {
            int b = m0 + ty * 4 + i;
            float gi = acc[i][0] + pg[i][0];
            float gf = acc[i][1] + pg[i][1];
            float gg = acc[i][2] + pg[i][2];
            float go = acc[i][3] + pg[i][3];
            float iv = sigf(gi), fv = sigf(gf);
            float gv = tanhf(gg), ov = sigf(go);
            cst[i] = fv * cst[i] + iv * gv;
            float h = ov * tanhf(cst[i]);
            hdst[(size_t)b * Dsz + d] = h;
            // inline bf16 hi/lo split of h (consumed directly by w-GEMM)
            size_t o = ((size_t)b * Ssz + t) * Dsz + d;
            __nv_bfloat16 hh = __float2bfloat16(h);
            g_rnnhi[o] = hh;
            g_rnnlo[o] = __float2bfloat16(h - __bfloat162float(hh));
        }
        groupBarrier(mb);
    }
}

// ---------------- attention + aligned + diffusion prep (+ inline split) ----------------
__global__ void attn_diff(const float* __restrict__ W2,
                          const float* __restrict__ b2,
                          const float* __restrict__ noise,
                          const float* __restrict__ temb,
                          const int* __restrict__ tdi)
{
    int s = blockIdx.x;
    int b = blockIdx.y;
    int tid = threadIdx.x;
    const float* ek = g_x + (size_t)b * Ssz * Dsz;
    size_t orow = ((size_t)b * Ssz + s) * Dsz;

    float av;
    if (s == 0) {
        av = ek[tid];
    } else {
        __shared__ float s0[64], s1[64];
        __shared__ float a0s, a1s;
        int sm1 = s - 1;
        if (tid < 64) {
            float f = tanhf(g_featE[b*64 + tid] + g_featW[((size_t)b*Ssz + sm1)*64 + tid]);
            s0[tid] = f * W2[tid];
            s1[tid] = f * W2[64 + tid];
        }
        __syncthreads();
        if (tid == 0) {
            float l0 = b2[0], l1 = b2[1];
            for (int j = 0; j < 64; j++) { l0 += s0[j]; l1 += s1[j]; }
            float m = fmaxf(l0, l1);
            float e0 = expf(l0 - m), e1 = expf(l1 - m);
            float inv = 1.f / (e0 + e1);
            a0s = e0 * inv; a1s = e1 * inv;
        }
        __syncthreads();
        float wv = g_w[((size_t)b * Ssz + sm1) * Dsz + tid];
        av = a0s * ek[tid] + a1s * wv;
    }
    g_aligned[orow + tid] = av;
    float al = g_alpha[b];
    float sa = sqrtf(al), sn = sqrtf(1.f - al);
    float pre = av * sa + noise[orow + tid] * sn
              + temb[(size_t)tdi[b] * Dsz + tid];
    __nv_bfloat16 h = __float2bfloat16(pre);
    g_prehi[orow + tid] = h;
    g_prelo[orow + tid] = __float2bfloat16(pre - __bfloat162float(h));
}

// ---------------- fused max-pool + final projections ----------------
__global__ void poolfinal(const float* __restrict__ noise,
                          const float* __restrict__ pn,
                          const float* __restrict__ Wout,
                          const float* __restrict__ bout,
                          float* __restrict__ out)
{
    int b = blockIdx.x, d = threadIdx.x;
    float xm = -INFINITY, gm = -INFINITY;
    for (int s = 0; s < Ssz; s++) {
        size_t i = ((size_t)b * Ssz + s) * Dsz + d;
        xm = fmaxf(xm, g_x[i]);
        float gv = g_aligned[i] + noise[i] - pn[i];
        gm = fmaxf(gm, gv);
    }
    __shared__ float4 red[256];
    red[d] = make_float4(xm * Wout[d], xm * Wout[Dsz + d],
                         gm * Wout[d], gm * Wout[Dsz + d]);
    __syncthreads();
    for (int off = 128; off > 0; off >>= 1) {
        if (d < off) {
            float4 a = red[d], c = red[d + off];
            red[d] = make_float4(a.x + c.x, a.y + c.y, a.z + c.z, a.w + c.w);
        }
        __syncthreads();
    }
    if (d == 0) {
        float4 r = red[0];
        out[b*2 + 0]         = r.x + bout[0];
        out[b*2 + 1]         = r.y + bout[1];
        out[2*Bsz + b*2 + 0] = r.z + bout[0];
        out[2*Bsz + b*2 + 1] = r.w + bout[1];
    }
}

// ---------------- host ----------------
static float* symf(const void* s)
{
    void* p = nullptr;
    cudaGetSymbolAddress(&p, s);
    return (float*)p;
}
static __nv_bfloat16* symb(const void* s)
{
    void* p = nullptr;
    cudaGetSymbolAddress(&p, s);
    return (__nv_bfloat16*)p;
}

extern "C" void kernel_launch(void* const* d_in, const int* in_sizes, int n_in,
                              void* d_out, int out_size)
{
    const int*   seqs   = (const int*)  d_in[0];
    const int*   tdiff  = (const int*)  d_in[5];
    const float* noise  = (const float*)d_in[6];
    const float* emb    = (const float*)d_in[7];
    const float* Wih    = (const float*)d_in[8];
    const float* Whh    = (const float*)d_in[9];
    const float* bih    = (const float*)d_in[10];
    const float* bhh    = (const float*)d_in[11];
    const float* Whk    = (const float*)d_in[12];
    const float* bhk    = (const float*)d_in[13];
    const float* W1     = (const float*)d_in[14];
    const float* b1     = (const float*)d_in[15];
    const float* W2     = (const float*)d_in[16];
    const float* b2     = (const float*)d_in[17];
    const float* Wdiff  = (const float*)d_in[18];
    const float* bdiff  = (const float*)d_in[19];
    const float* temb   = (const float*)d_in[20];
    const float* Wout   = (const float*)d_in[21];
    const float* bout   = (const float*)d_in[22];
    float* out = (float*)d_out;

    float* p_x    = symf(g_x);
    float* p_Gih  = symf(g_Gih);
    float* p_w    = symf(g_w);
    float* p_fE   = symf(g_featE);
    float* p_fW   = symf(g_featW);
    float* p_bsum = symf(g_bsum);

    __nv_bfloat16* p_xhi   = symb(g_xhi);
    __nv_bfloat16* p_xlo   = symb(g_xlo);
    __nv_bfloat16* p_rhi   = symb(g_rnnhi);
    __nv_bfloat16* p_rlo   = symb(g_rnnlo);
    __nv_bfloat16* p_phi   = symb(g_prehi);
    __nv_bfloat16* p_plo   = symb(g_prelo);
    __nv_bfloat16* p_Wihhi = symb(g_Wihhi);
    __nv_bfloat16* p_Wihlo = symb(g_Wihlo);
    __nv_bfloat16* p_Whkhi = symb(g_Whkhi);
    __nv_bfloat16* p_Whklo = symb(g_Whklo);
    __nv_bfloat16* p_Wdhi  = symb(g_Wdhi);
    __nv_bfloat16* p_Wdlo  = symb(g_Wdlo);

    static bool attr_done = false;
    if (!attr_done) {
        cudaFuncSetAttribute(lstm_fused,
                             cudaFuncAttributeMaxDynamicSharedMemorySize, LSTM_SMEM);
        cudaFuncSetAttribute(gemm_mma,
                             cudaFuncAttributeMaxDynamicSharedMemorySize, GM_SMEM);
        attr_done = true;
    }

    const int BSD = Bsz * Ssz * Dsz;
    float* pn_out = out + 4 * Bsz;
    float* nn_out = out + 4 * Bsz + (size_t)BSD;

    alpha_kernel<<<1, 256>>>(tdiff);
    bsum_kernel<<<4, 256>>>(bih, bhh);
    transpose_wdiff<<<Dsz, Dsz>>>(Wdiff);
    wsplit_all<<<(6*DD)/256, 256>>>(Wih, Whk);

    // embedding (+ inline split)
    embed_kernel<<<Bsz * Ssz, Dsz>>>(seqs, emb);

    // Gih = x @ Wih^T + (bih+bhh)   (12800 x 1024, HMMA)
    gemm_mma<<<dim3(8, 100), 256, GM_SMEM>>>(p_xhi, p_xlo, p_Wihhi, p_Wihlo,
                                             p_bsum, p_Gih, 4*Dsz);

    // fused persistent LSTM (128 thr; writes split h inline)
    lstm_fused<<<dim3(LSTM_GX, LSTM_GY), 128, LSTM_SMEM>>>(Whh);

    // w = rnn @ Whk^T + bhk   (consumes split rnn directly)
    gemm_mma<<<dim3(2, 100), 256, GM_SMEM>>>(p_rhi, p_rlo, p_Whkhi, p_Whklo,
                                             bhk, p_w, Dsz);

    // attention features (N=64, scalar GEMM)
    gemm_nt<<<dim3(1, Bsz/64), 256>>>(Bsz, 64, Dsz,
        p_x, Ssz * Dsz, W1, 2 * Dsz, b1, p_fE, 64);
    gemm_nt<<<dim3(1, (Bsz*Ssz)/64), 256>>>(Bsz*Ssz, 64, Dsz,
        p_w, Dsz, W1 + Dsz, 2 * Dsz, nullptr, p_fW, 64);

    // attention softmax + aligned + diffusion prep (+ inline split)
    attn_diff<<<dim3(Ssz, Bsz), Dsz>>>(W2, b2, noise, temb, tdiff);

    // predicted_noise = pre @ Wdiff + bdiff
    gemm_mma<<<dim3(2, 100), 256, GM_SMEM>>>(p_phi, p_plo, p_Wdhi, p_Wdlo,
                                             bdiff, pn_out, Dsz);

    // fused pool + final
    poolfinal<<<Bsz, Dsz>>>(noise, pn_out, Wout, bout, out);

    // normal_noise passthrough
    cudaMemcpyAsync(nn_out, noise, (size_t)BSD * sizeof(float),
                    cudaMemcpyDeviceToDevice);
}

// round 15
// speedup vs baseline: 1.1010x; 1.0386x over previous
#include <cuda_runtime.h>
#include <cuda_bf16.h>
#include <math.h>

#define Bsz 256
#define Ssz 50
#define Csz 40
#define Dsz 256
#define TDIFF 1000

#define LSTM_GX 16   // gate-col blocks: 64 permuted cols (16 h-dims) each
#define LSTM_GY 8    // batch blocks: 32 rows each

// ---------------- scratch ----------------
__device__ float g_x[Bsz*Ssz*Dsz];
__device__ float g_Gih[Bsz*Ssz*4*Dsz];      // x@WihP^T + bsumP (permuted cols p=d*4+g)
__device__ float g_w[Bsz*Ssz*Dsz];
__device__ float g_featE[Bsz*64];
__device__ float g_featW[Bsz*Ssz*64];
__device__ float g_aligned[Bsz*Ssz*Dsz];
__device__ float g_alpha[Bsz];
__device__ float g_WdiffT[Dsz*Dsz];
__device__ float g_bsumP[4*Dsz];            // permuted bih+bhh

// bf16 split operands
__device__ __nv_bfloat16 g_xhi[Bsz*Ssz*Dsz],   g_xlo[Bsz*Ssz*Dsz];
__device__ __nv_bfloat16 g_rnnhi[Bsz*Ssz*Dsz], g_rnnlo[Bsz*Ssz*Dsz];
__device__ __nv_bfloat16 g_prehi[Bsz*Ssz*Dsz], g_prelo[Bsz*Ssz*Dsz];
__device__ __nv_bfloat16 g_WihPhi[4*Dsz*Dsz],  g_WihPlo[4*Dsz*Dsz];  // permuted rows
__device__ __nv_bfloat16 g_WrPhi[4*Dsz*Dsz],   g_WrPlo[4*Dsz*Dsz];   // permuted Whh
__device__ __nv_bfloat16 g_Whkhi[Dsz*Dsz],     g_Whklo[Dsz*Dsz];
__device__ __nv_bfloat16 g_Wdhi[Dsz*Dsz],      g_Wdlo[Dsz*Dsz];

__device__ unsigned g_barCnt[LSTM_GY];
__device__ volatile unsigned g_barGen[LSTM_GY];

// ================= helpers =================
__device__ __forceinline__ unsigned smem_u32(const void* p)
{
    unsigned a;
    asm("{ .reg .u64 t; cvta.to.shared.u64 t, %1; cvt.u32.u64 %0, t; }"
        : "=r"(a) : "l"(p));
    return a;
}

__device__ __forceinline__ void mma16816(float* c, const unsigned* a, const unsigned* b)
{
    asm volatile(
        "mma.sync.aligned.m16n8k16.row.col.f32.bf16.bf16.f32 "
        "{%0,%1,%2,%3}, {%4,%5,%6,%7}, {%8,%9}, {%0,%1,%2,%3};"
        : "+f"(c[0]), "+f"(c[1]), "+f"(c[2]), "+f"(c[3])
        : "r"(a[0]), "r"(a[1]), "r"(a[2]), "r"(a[3]), "r"(b[0]), "r"(b[1]));
}

__device__ __forceinline__ void ldsm_x4(unsigned* d, unsigned saddr)
{
    asm volatile("ldmatrix.sync.aligned.m8n8.x4.shared.b16 {%0,%1,%2,%3}, [%4];"
                 : "=r"(d[0]), "=r"(d[1]), "=r"(d[2]), "=r"(d[3]) : "r"(saddr));
}

// ================= mma.sync bf16 split-GEMM (round-12 proven) =================
#define GPAD 72
#define GTILE (128*GPAD)
#define GM_SMEM (4*GTILE*2)

__global__ void __launch_bounds__(256, 1)
gemm_mma(const __nv_bfloat16* __restrict__ Ahi, const __nv_bfloat16* __restrict__ Alo,
         const __nv_bfloat16* __restrict__ Bhi, const __nv_bfloat16* __restrict__ Blo,
         const float* __restrict__ bias, float* __restrict__ C, int ldc)
{
    extern __shared__ __nv_bfloat16 sm[];
    __nv_bfloat16* sAh = sm;
    __nv_bfloat16* sAl = sAh + GTILE;
    __nv_bfloat16* sBh = sAl + GTILE;
    __nv_bfloat16* sBl = sBh + GTILE;

    const int tid = threadIdx.x;
    const int w   = tid >> 5;
    const int l   = tid & 31;
    const int wm  = (w >> 1) * 32;
    const int wn  = (w & 1) * 64;
    const int r   = l >> 2;
    const int q   = l & 3;
    const int m0  = blockIdx.y * 128;
    const int n0  = blockIdx.x * 128;

    float acc[2][8][4];
    #pragma unroll
    for (int mi = 0; mi < 2; mi++)
        #pragma unroll
        for (int ni = 0; ni < 8; ni++)
            #pragma unroll
            for (int e = 0; e < 4; e++) acc[mi][ni][e] = 0.f;

    const int srow = tid >> 1;
    const int scol = (tid & 1) * 32;

    for (int kc = 0; kc < 256; kc += 64) {
        {
            size_t goffA = (size_t)(m0 + srow) * 256 + kc + scol;
            size_t goffB = (size_t)(n0 + srow) * 256 + kc + scol;
            int soff = srow * GPAD + scol;
            #pragma unroll
            for (int v = 0; v < 4; v++) {
                *(uint4*)(sAh + soff + v*8) = *(const uint4*)(Ahi + goffA + v*8);
                *(uint4*)(sAl + soff + v*8) = *(const uint4*)(Alo + goffA + v*8);
                *(uint4*)(sBh + soff + v*8) = *(const uint4*)(Bhi + goffB + v*8);
                *(uint4*)(sBl + soff + v*8) = *(const uint4*)(Blo + goffB + v*8);
            }
        }
        __syncthreads();

        #pragma unroll
        for (int kk = 0; kk < 4; kk++) {
            const int kb = kk * 16 + 2 * q;
            unsigned ah[2][4], al[2][4], bh[8][2], bl[8][2];
            #pragma unroll
            for (int mi = 0; mi < 2; mi++) {
                int base = (wm + mi*16 + r) * GPAD + kb;
                ah[mi][0] = *(const unsigned*)(sAh + base);
                ah[mi][1] = *(const unsigned*)(sAh + base + 8*GPAD);
                ah[mi][2] = *(const unsigned*)(sAh + base + 8);
                ah[mi][3] = *(const unsigned*)(sAh + base + 8*GPAD + 8);
                al[mi][0] = *(const unsigned*)(sAl + base);
                al[mi][1] = *(const unsigned*)(sAl + base + 8*GPAD);
                al[mi][2] = *(const unsigned*)(sAl + base + 8);
                al[mi][3] = *(const unsigned*)(sAl + base + 8*GPAD + 8);
            }
            #pragma unroll
            for (int ni = 0; ni < 8; ni++) {
                int base = (wn + ni*8 + r) * GPAD + kb;
                bh[ni][0] = *(const unsigned*)(sBh + base);
                bh[ni][1] = *(const unsigned*)(sBh + base + 8);
                bl[ni][0] = *(const unsigned*)(sBl + base);
                bl[ni][1] = *(const unsigned*)(sBl + base + 8);
            }
            #pragma unroll
            for (int mi = 0; mi < 2; mi++)
                #pragma unroll
                for (int ni = 0; ni < 8; ni++) {
                    mma16816(acc[mi][ni], ah[mi], bh[ni]);
                    mma16816(acc[mi][ni], ah[mi], bl[ni]);
                    mma16816(acc[mi][ni], al[mi], bh[ni]);
                }
        }
        __syncthreads();
    }

    #pragma unroll
    for (int mi = 0; mi < 2; mi++) {
        int row = m0 + wm + mi*16 + r;
        #pragma unroll
        for (int ni = 0; ni < 8; ni++) {
            int col = n0 + wn + ni*8 + 2*q;
            float b0 = bias[col], b1 = bias[col + 1];
            *(float2*)(C + (size_t)row * ldc + col) =
                make_float2(acc[mi][ni][0] + b0, acc[mi][ni][1] + b1);
            *(float2*)(C + (size_t)(row + 8) * ldc + col) =
                make_float2(acc[mi][ni][2] + b0, acc[mi][ni][3] + b1);
        }
    }
}

// ================= persistent LSTM on HMMA + ldmatrix =================
// Grid (16, 8), 128 thr. CTA: 32 batch x 64 permuted gate-cols (16 h-dims).
#define LPAD 264
#define LSTM2_SMEM ((64*LPAD*2 + 32*LPAD*2) * 2)    // 101376 bytes

__device__ __forceinline__ float sigf(float x) { return 1.f / (1.f + expf(-x)); }

__device__ __forceinline__ void groupBarrier(int grp)
{
    __syncthreads();
    if (threadIdx.x == 0) {
        __threadfence();
        unsigned gen = g_barGen[grp];
        __threadfence();
        if (atomicAdd(&g_barCnt[grp], 1u) == LSTM_GX - 1) {
            g_barCnt[grp] = 0;
            __threadfence();
            g_barGen[grp] = gen + 1;
        } else {
            while (g_barGen[grp] == gen) __nanosleep(32);
        }
        __threadfence();
    }
    __syncthreads();
}

__global__ void __launch_bounds__(128, 1)
lstm_mma()
{
    extern __shared__ __nv_bfloat16 ls[];
    __nv_bfloat16* sWh = ls;                  // [64][LPAD]
    __nv_bfloat16* sWl = sWh + 64*LPAD;
    __nv_bfloat16* sHh = sWl + 64*LPAD;       // [32][LPAD]
    __nv_bfloat16* sHl = sHh + 32*LPAD;

    const int tid = threadIdx.x;
    const int w   = tid >> 5;
    const int l   = tid & 31;
    const int r   = l >> 2;
    const int q   = l & 3;
    const int wm  = (w >> 1) * 16;   // warp m: {0,16}
    const int wn  = (w & 1) * 32;    // warp n: {0,32} gate-col rows
    const int nb  = blockIdx.x;
    const int mb  = blockIdx.y;
    const int m0  = mb * 32;

    // one-time: load permuted Whh split slice (rows nb*64 .. +63)
    for (int i = tid; i < 64*32; i += 128) {
        int pr = i >> 5;
        int k8 = (i & 31) * 8;
        *(uint4*)(sWh + pr*LPAD + k8) =
            *(const uint4*)(g_WrPhi + (size_t)(nb*64 + pr)*256 + k8);
        *(uint4*)(sWl + pr*LPAD + k8) =
            *(const uint4*)(g_WrPlo + (size_t)(nb*64 + pr)*256 + k8);
    }

    // per-lane ldmatrix offsets (bf16 element units)
    const int frag_row = (l & 7) + ((l >> 3) & 1) * 8;
    const int frag_col = (l >> 4) * 8;
    const unsigned aoff = (unsigned)((wm + frag_row) * LPAD + frag_col);
    const unsigned boff = (unsigned)((wn + frag_row) * LPAD + frag_col);
    const unsigned uHh = smem_u32(sHh), uHl = smem_u32(sHl);
    const unsigned uWh = smem_u32(sWh), uWl = smem_u32(sWl);

    float cst[4][2];
    #pragma unroll
    for (int ni = 0; ni < 4; ni++) { cst[ni][0] = 0.f; cst[ni][1] = 0.f; }
    __syncthreads();

    for (int t = 0; t < Ssz; t++) {
        // prefetch permuted Gih operands
        const int row0 = m0 + wm + r;
        float2 pgA[4], pgB[4];
        #pragma unroll
        for (int ni = 0; ni < 4; ni++) {
            int pgc = nb*64 + wn + ni*8 + 2*q;
            pgA[ni] = *(const float2*)(g_Gih + ((size_t)row0 * Ssz + t) * 1024 + pgc);
            pgB[ni] = *(const float2*)(g_Gih + ((size_t)(row0 + 8) * Ssz + t) * 1024 + pgc);
        }

        float acc[4][4];
        #pragma unroll
        for (int ni = 0; ni < 4; ni++)
            #pragma unroll
            for (int e = 0; e < 4; e++) acc[ni][e] = 0.f;

        if (t > 0) {
            // stage h(t-1) split tile: 32 rows x 256
            {
                int rr = tid >> 2;
                int c64 = (tid & 3) * 64;
                size_t src = ((size_t)(m0 + rr) * Ssz + (t - 1)) * 256 + c64;
                int dst = rr * LPAD + c64;
                #pragma unroll
                for (int v = 0; v < 8; v++) {
                    *(uint4*)(sHh + dst + v*8) = *(const uint4*)(g_rnnhi + src + v*8);
                    *(uint4*)(sHl + dst + v*8) = *(const uint4*)(g_rnnlo + src + v*8);
                }
            }
            __syncthreads();

            #pragma unroll
            for (int kk = 0; kk < 16; kk++) {
                const unsigned kb = kk * 16;
                unsigned ah[4], al[4], r0h[4], r1h[4], r0l[4], r1l[4];
                ldsm_x4(ah,  uHh + (aoff + kb) * 2);
                ldsm_x4(al,  uHl + (aoff + kb) * 2);
                ldsm_x4(r0h, uWh + (boff + kb) * 2);
                ldsm_x4(r1h, uWh + (boff + 16*LPAD + kb) * 2);
                ldsm_x4(r0l, uWl + (boff + kb) * 2);
                ldsm_x4(r1l, uWl + (boff + 16*LPAD + kb) * 2);
                // x4 output: r0=b0(ntile even), r1=b0(ntile odd), r2=b1(even), r3=b1(odd)
                unsigned bh[4][2] = {{r0h[0], r0h[2]}, {r0h[1], r0h[3]},
                                     {r1h[0], r1h[2]}, {r1h[1], r1h[3]}};
                unsigned bl[4][2] = {{r0l[0], r0l[2]}, {r0l[1], r0l[3]},
                                     {r1l[0], r1l[2]}, {r1l[1], r1l[3]}};
                #pragma unroll
                for (int ni = 0; ni < 4; ni++) {
                    mma16816(acc[ni], ah, bh[ni]);
                    mma16816(acc[ni], ah, bl[ni]);
                    mma16816(acc[ni], al, bh[ni]);
                }
            }
        }

        // epilogue: + permuted Gih, shfl gate-exchange, c/h update, split h store
        #pragma unroll
        for (int ni = 0; ni < 4; ni++) {
            float p0 = acc[ni][0] + pgA[ni].x;
            float p1 = acc[ni][1] + pgA[ni].y;
            float p2 = acc[ni][2] + pgB[ni].x;
            float p3 = acc[ni][3] + pgB[ni].y;
            float r0 = __shfl_xor_sync(0xffffffffu, p0, 1);
            float r1 = __shfl_xor_sync(0xffffffffu, p1, 1);
            float r2 = __shfl_xor_sync(0xffffffffu, p2, 1);
            float r3 = __shfl_xor_sync(0xffffffffu, p3, 1);
            float iA, fA, gA, oA, iB, fB, gB, oB;
            if ((q & 1) == 0) { iA = p0; fA = p1; gA = r0; oA = r1;
                                iB = p2; fB = p3; gB = r2; oB = r3; }
            else              { iA = r0; fA = r1; gA = p0; oA = p1;
                                iB = r2; fB = r3; gB = p2; oB = p3; }
            cst[ni][0] = sigf(fA) * cst[ni][0] + sigf(iA) * tanhf(gA);
            cst[ni][1] = sigf(fB) * cst[ni][1] + sigf(iB) * tanhf(gB);
            float h0 = sigf(oA) * tanhf(cst[ni][0]);
            float h1 = sigf(oB) * tanhf(cst[ni][1]);
            int d = nb*16 + ((wn + ni*8) >> 2) + (q >> 1);
            size_t o0 = ((size_t)row0 * Ssz + t) * 256 + d;
            size_t o1 = ((size_t)(row0 + 8) * Ssz + t) * 256 + d;
            __nv_bfloat16 h0h = __float2bfloat16(h0);
            __nv_bfloat16 h1h = __float2bfloat16(h1);
            if ((q & 1) == 0) {
                g_rnnhi[o0] = h0h;
                g_rnnhi[o1] = h1h;
            } else {
                g_rnnlo[o0] = __float2bfloat16(h0 - __bfloat162float(h0h));
                g_rnnlo[o1] = __float2bfloat16(h1 - __bfloat162float(h1h));
            }
        }
        groupBarrier(mb);
    }
}

// ---------------- prep: permute+split weights (p = d*4+g; round-11 verified) ----------------
__global__ void prep_perm(const float* __restrict__ W,
                          __nv_bfloat16* __restrict__ hi,
                          __nv_bfloat16* __restrict__ lo,
                          const float* __restrict__ bih,
                          const float* __restrict__ bhh,
                          float* __restrict__ biasP)
{
    int p = blockIdx.x;
    int k = threadIdx.x;
    int d = p >> 2, g = p & 3;
    int src = g * 256 + d;
    float v = W[(size_t)src * 256 + k];
    __nv_bfloat16 h = __float2bfloat16(v);
    hi[(size_t)p * 256 + k] = h;
    lo[(size_t)p * 256 + k] = __float2bfloat16(v - __bfloat162float(h));
    if (biasP && k == 0) biasP[p] = bih[src] + bhh[src];
}

// ---------------- split Whk + WdiffT ----------------
#define DD (Dsz*Dsz)
__global__ void wsplit2(const float* __restrict__ Whk)
{
    int i = blockIdx.x * 256 + threadIdx.x;
    float x;
    __nv_bfloat16 *hi, *lo;
    int idx;
    if (i < DD) { idx = i;      x = Whk[idx];      hi = g_Whkhi; lo = g_Whklo; }
    else        { idx = i - DD; x = g_WdiffT[idx]; hi = g_Wdhi;  lo = g_Wdlo; }
    __nv_bfloat16 h = __float2bfloat16(x);
    hi[idx] = h;
    lo[idx] = __float2bfloat16(x - __bfloat162float(h));
}

// ================= 64x64 NT GEMM (N=64 feature GEMMs) =================
__global__ void gemm_nt(int M, int N, int K,
                        const float* __restrict__ A, int lda,
                        const float* __restrict__ B, int ldb,
                        const float* __restrict__ bias,
                        float* __restrict__ C, int ldc)
{
    __shared__ float As[16][68];
    __shared__ float Bsh[16][68];
    const int tid = threadIdx.x;
    const int m0 = blockIdx.y * 64;
    const int n0 = blockIdx.x * 64;
    const int tx = tid & 15;
    const int ty = tid >> 4;
    const int lr = tid >> 2;
    const int lc = (tid & 3) * 4;

    float acc[4][4] = {};
    for (int k0 = 0; k0 < K; k0 += 16) {
        float4 a4 = *(const float4*)(A + (size_t)(m0 + lr) * lda + k0 + lc);
        float4 b4 = *(const float4*)(B + (size_t)(n0 + lr) * ldb + k0 + lc);
        As[lc+0][lr] = a4.x; As[lc+1][lr] = a4.y; As[lc+2][lr] = a4.z; As[lc+3][lr] = a4.w;
        Bsh[lc+0][lr] = b4.x; Bsh[lc+1][lr] = b4.y; Bsh[lc+2][lr] = b4.z; Bsh[lc+3][lr] = b4.w;
        __syncthreads();
        #pragma unroll
        for (int k = 0; k < 16; k++) {
            float a[4], b[4];
            #pragma unroll
            for (int i = 0; i < 4; i++) a[i] = As[k][ty*4 + i];
            #pragma unroll
            for (int j = 0; j < 4; j++) b[j] = Bsh[k][tx*4 + j];
            #pragma unroll
            for (int i = 0; i < 4; i++)
                #pragma unroll
                for (int j = 0; j < 4; j++)
                    acc[i][j] = fmaf(a[i], b[j], acc[i][j]);
        }
        __syncthreads();
    }
    #pragma unroll
    for (int i = 0; i < 4; i++) {
        int row = m0 + ty*4 + i;
        #pragma unroll
        for (int j = 0; j < 4; j++) {
            int col = n0 + tx*4 + j;
            float v = acc[i][j];
            if (bias) v += bias[col];
            C[(size_t)row * ldc + col] = v;
        }
    }
}

// ---------------- embedding gather-sum (+ inline split) ----------------
__global__ void embed_kernel(const int* __restrict__ seqs,
                             const float* __restrict__ emb)
{
    int bs = blockIdx.x;
    int d  = threadIdx.x;
    __shared__ int idx[Csz];
    if (threadIdx.x < Csz) idx[threadIdx.x] = seqs[bs * Csz + threadIdx.x];
    __syncthreads();
    float acc = 0.f;
    #pragma unroll 8
    for (int c = 0; c < Csz; c++)
        acc += __ldg(emb + (size_t)idx[c] * Dsz + d);
    size_t o = (size_t)bs * Dsz + d;
    g_x[o] = acc;
    __nv_bfloat16 h = __float2bfloat16(acc);
    g_xhi[o] = h;
    g_xlo[o] = __float2bfloat16(acc - __bfloat162float(h));
}

// ---------------- alpha lookup ----------------
__global__ void alpha_kernel(const int* __restrict__ t)
{
    __shared__ float tab[TDIFF];
    if (threadIdx.x == 0) {
        float a = 1.f;
        for (int i = 0; i < TDIFF; i++) {
            float beta = 1e-4f + (0.02f - 1e-4f) * (float)i / (float)(TDIFF - 1);
            a *= (1.f - beta);
            tab[i] = a;
        }
    }
    __syncthreads();
    if (threadIdx.x < Bsz) g_alpha[threadIdx.x] = tab[t[threadIdx.x]];
}

__global__ void transpose_wdiff(const float* __restrict__ Wdiff)
{
    int n = blockIdx.x, k = threadIdx.x;
    g_WdiffT[n * Dsz + k] = __ldg(Wdiff + k * Dsz + n);
}

// ---------------- attention + aligned + diffusion prep (+ inline split) ----------------
__global__ void attn_diff(const float* __restrict__ W2,
                          const float* __restrict__ b2,
                          const float* __restrict__ noise,
                          const float* __restrict__ temb,
                          const int* __restrict__ tdi)
{
    int s = blockIdx.x;
    int b = blockIdx.y;
    int tid = threadIdx.x;
    const float* ek = g_x + (size_t)b * Ssz * Dsz;
    size_t orow = ((size_t)b * Ssz + s) * Dsz;

    float av;
    if (s == 0) {
        av = ek[tid];
    } else {
        __shared__ float s0[64], s1[64];
        __shared__ float a0s, a1s;
        int sm1 = s - 1;
        if (tid < 64) {
            float f = tanhf(g_featE[b*64 + tid] + g_featW[((size_t)b*Ssz + sm1)*64 + tid]);
            s0[tid] = f * W2[tid];
            s1[tid] = f * W2[64 + tid];
        }
        __syncthreads();
        if (tid == 0) {
            float l0 = b2[0], l1 = b2[1];
            for (int j = 0; j < 64; j++) { l0 += s0[j]; l1 += s1[j]; }
            float m = fmaxf(l0, l1);
            float e0 = expf(l0 - m), e1 = expf(l1 - m);
            float inv = 1.f / (e0 + e1);
            a0s = e0 * inv; a1s = e1 * inv;
        }
        __syncthreads();
        float wv = g_w[((size_t)b * Ssz + sm1) * Dsz + tid];
        av = a0s * ek[tid] + a1s * wv;
    }
    g_aligned[orow + tid] = av;
    float al = g_alpha[b];
    float sa = sqrtf(al), sn = sqrtf(1.f - al);
    float pre = av * sa + noise[orow + tid] * sn
              + temb[(size_t)tdi[b] * Dsz + tid];
    __nv_bfloat16 h = __float2bfloat16(pre);
    g_prehi[orow + tid] = h;
    g_prelo[orow + tid] = __float2bfloat16(pre - __bfloat162float(h));
}

// ---------------- fused max-pool + final projections ----------------
__global__ void poolfinal(const float* __restrict__ noise,
                          const float* __restrict__ pn,
                          const float* __restrict__ Wout,
                          const float* __restrict__ bout,
                          float* __restrict__ out)
{
    int b = blockIdx.x, d = threadIdx.x;
    float xm = -INFINITY, gm = -INFINITY;
    for (int s = 0; s < Ssz; s++) {
        size_t i = ((size_t)b * Ssz + s) * Dsz + d;
        xm = fmaxf(xm, g_x[i]);
        float gv = g_aligned[i] + noise[i] - pn[i];
        gm = fmaxf(gm, gv);
    }
    __shared__ float4 red[256];
    red[d] = make_float4(xm * Wout[d], xm * Wout[Dsz + d],
                         gm * Wout[d], gm * Wout[Dsz + d]);
    __syncthreads();
    for (int off = 128; off > 0; off >>= 1) {
        if (d < off) {
            float4 a = red[d], c = red[d + off];
            red[d] = make_float4(a.x + c.x, a.y + c.y, a.z + c.z, a.w + c.w);
        }
        __syncthreads();
    }
    if (d == 0) {
        float4 r = red[0];
        out[b*2 + 0]         = r.x + bout[0];
        out[b*2 + 1]         = r.y + bout[1];
        out[2*Bsz + b*2 + 0] = r.z + bout[0];
        out[2*Bsz + b*2 + 1] = r.w + bout[1];
    }
}

// ---------------- host ----------------
static float* symf(const void* s)
{
    void* p = nullptr;
    cudaGetSymbolAddress(&p, s);
    return (float*)p;
}
static __nv_bfloat16* symb(const void* s)
{
    void* p = nullptr;
    cudaGetSymbolAddress(&p, s);
    return (__nv_bfloat16*)p;
}

extern "C" void kernel_launch(void* const* d_in, const int* in_sizes, int n_in,
                              void* d_out, int out_size)
{
    const int*   seqs   = (const int*)  d_in[0];
    const int*   tdiff  = (const int*)  d_in[5];
    const float* noise  = (const float*)d_in[6];
    const float* emb    = (const float*)d_in[7];
    const float* Wih    = (const float*)d_in[8];
    const float* Whh    = (const float*)d_in[9];
    const float* bih    = (const float*)d_in[10];
    const float* bhh    = (const float*)d_in[11];
    const float* Whk    = (const float*)d_in[12];
    const float* bhk    = (const float*)d_in[13];
    const float* W1     = (const float*)d_in[14];
    const float* b1     = (const float*)d_in[15];
    const float* W2     = (const float*)d_in[16];
    const float* b2     = (const float*)d_in[17];
    const float* Wdiff  = (const float*)d_in[18];
    const float* bdiff  = (const float*)d_in[19];
    const float* temb   = (const float*)d_in[20];
    const float* Wout   = (const float*)d_in[21];
    const float* bout   = (const float*)d_in[22];
    float* out = (float*)d_out;

    float* p_x     = symf(g_x);
    float* p_Gih   = symf(g_Gih);
    float* p_w     = symf(g_w);
    float* p_fE    = symf(g_featE);
    float* p_fW    = symf(g_featW);
    float* p_bsumP = symf(g_bsumP);

    __nv_bfloat16* p_xhi    = symb(g_xhi);
    __nv_bfloat16* p_xlo    = symb(g_xlo);
    __nv_bfloat16* p_rhi    = symb(g_rnnhi);
    __nv_bfloat16* p_rlo    = symb(g_rnnlo);
    __nv_bfloat16* p_phi    = symb(g_prehi);
    __nv_bfloat16* p_plo    = symb(g_prelo);
    __nv_bfloat16* p_WihPhi = symb(g_WihPhi);
    __nv_bfloat16* p_WihPlo = symb(g_WihPlo);
    __nv_bfloat16* p_WrPhi  = symb(g_WrPhi);
    __nv_bfloat16* p_WrPlo  = symb(g_WrPlo);
    __nv_bfloat16* p_Whkhi  = symb(g_Whkhi);
    __nv_bfloat16* p_Whklo  = symb(g_Whklo);
    __nv_bfloat16* p_Wdhi   = symb(g_Wdhi);
    __nv_bfloat16* p_Wdlo   = symb(g_Wdlo);

    static bool attr_done = false;
    if (!attr_done) {
        cudaFuncSetAttribute(gemm_mma,
                             cudaFuncAttributeMaxDynamicSharedMemorySize, GM_SMEM);
        cudaFuncSetAttribute(lstm_mma,
                             cudaFuncAttributeMaxDynamicSharedMemorySize, LSTM2_SMEM);
        attr_done = true;
    }

    const int BSD = Bsz * Ssz * Dsz;
    float* pn_out = out + 4 * Bsz;
    float* nn_out = out + 4 * Bsz + (size_t)BSD;

    alpha_kernel<<<1, 256>>>(tdiff);
    transpose_wdiff<<<Dsz, Dsz>>>(Wdiff);
    wsplit2<<<(2*DD)/256, 256>>>(Whk);
    prep_perm<<<1024, 256>>>(Wih, p_WihPhi, p_WihPlo, bih, bhh, p_bsumP);
    prep_perm<<<1024, 256>>>(Whh, p_WrPhi, p_WrPlo, nullptr, nullptr, nullptr);

    // embedding (+ inline split)
    embed_kernel<<<Bsz * Ssz, Dsz>>>(seqs, emb);

    // Gih = x @ WihP^T + bsumP   (12800 x 1024, HMMA, permuted cols)
    gemm_mma<<<dim3(8, 100), 256, GM_SMEM>>>(p_xhi, p_xlo, p_WihPhi, p_WihPlo,
                                             p_bsumP, p_Gih, 4*Dsz);

    // persistent LSTM on HMMA + ldmatrix (writes split h directly)
    lstm_mma<<<dim3(LSTM_GX, LSTM_GY), 128, LSTM2_SMEM>>>();

    // w = rnn @ Whk^T + bhk   (consumes split rnn)
    gemm_mma<<<dim3(2, 100), 256, GM_SMEM>>>(p_rhi, p_rlo, p_Whkhi, p_Whklo,
                                             bhk, p_w, Dsz);

    // attention features (N=64, scalar GEMM)
    gemm_nt<<<dim3(1, Bsz/64), 256>>>(Bsz, 64, Dsz,
        p_x, Ssz * Dsz, W1, 2 * Dsz, b1, p_fE, 64);
    gemm_nt<<<dim3(1, (Bsz*Ssz)/64), 256>>>(Bsz*Ssz, 64, Dsz,
        p_w, Dsz, W1 + Dsz, 2 * Dsz, nullptr, p_fW, 64);

    // attention softmax + aligned + diffusion prep (+ inline split)
    attn_diff<<<dim3(Ssz, Bsz), Dsz>>>(W2, b2, noise, temb, tdiff);

    // predicted_noise = pre @ Wdiff + bdiff
    gemm_mma<<<dim3(2, 100), 256, GM_SMEM>>>(p_phi, p_plo, p_Wdhi, p_Wdlo,
                                             bdiff, pn_out, Dsz);

    // fused pool + final
    poolfinal<<<Bsz, Dsz>>>(noise, pn_out, Wout, bout, out);

    // normal_noise passthrough
    cudaMemcpyAsync(nn_out, noise, (size_t)BSD * sizeof(float),
                    cudaMemcpyDeviceToDevice);
}